// round 7
// baseline (speedup 1.0000x reference)
#include <cuda_runtime.h>
#include <cstdint>

#define NROWS  512
#define INSIZE 512
#define KK     64
#define DD     16
#define MM     (KK * DD)        // 1024
#define OUTW   (INSIZE + KK)    // 576
#define T      64               // pairwise tile size
#define PART   (NROWS * MM)     // one split-K partial, K-major [k][row][d]
#define PARTO  (NROWS * KK)     // one output-slot partial [k][i]

typedef unsigned long long ull;

__device__ float g_xT[INSIZE * NROWS];      // [k][row]          1 MB
__device__ float g_Wdup[INSIZE * 2 * MM];   // [k][2*col] dup    4 MB
__device__ float g_P[4 * PART];             // split-K partials  8 MB
__device__ float g_feat[NROWS * MM];        // k-major feat      2 MB
__device__ float g_part[8 * PARTO];         // output slots      1 MB

// ---------------------------------------------------------------------------
// helpers
// ---------------------------------------------------------------------------
__device__ __forceinline__ ull addf32x2(ull a, ull b) {
    ull r;
    asm("add.rn.f32x2 %0, %1, %2;" : "=l"(r) : "l"(a), "l"(b));
    return r;
}
__device__ __forceinline__ ull fmaf32x2(ull a, ull b, ull c) {
    ull r;
    asm("fma.rn.f32x2 %0, %1, %2, %3;" : "=l"(r) : "l"(a), "l"(b), "l"(c));
    return r;
}
__device__ __forceinline__ float lo32(ull v) {
    return __uint_as_float((unsigned int)v);
}
__device__ __forceinline__ float hi32(ull v) {
    return __uint_as_float((unsigned int)(v >> 32));
}
__device__ __forceinline__ float ex2f(float v) {
    float r;
    asm("ex2.approx.f32 %0, %1;" : "=f"(r) : "f"(v));
    return r;
}
__device__ __forceinline__ unsigned su32(const void* p) {
    return (unsigned)__cvta_generic_to_shared(p);
}
#define CPA16(dst, src) \
    asm volatile("cp.async.cg.shared.global [%0], [%1], 16;" :: "r"(dst), "l"(src))
#define CPA_COMMIT() asm volatile("cp.async.commit_group;")
#define CPA_WAIT1()  asm volatile("cp.async.wait_group 1;")

#define NLOG2E (-1.4426950408889634f)

// ---------------------------------------------------------------------------
// Kernel 0: prep. blocks 0..255: x -> g_xT (transpose) + x -> out copy.
//           blocks 256..767: W -> g_Wdup (transpose + duplicate cols).
// ---------------------------------------------------------------------------
__global__ __launch_bounds__(256)
void prep_kernel(const float* __restrict__ x, const float* __restrict__ W,
                 float* __restrict__ out) {
    __shared__ float sm[32][33];
    const int tid = threadIdx.x;
    const int tc = tid & 31, tr = tid >> 5;

    if (blockIdx.x < 256) {
        const int k0 = (blockIdx.x & 15) * 32;
        const int r0 = (blockIdx.x >> 4) * 32;
#pragma unroll
        for (int rr = 0; rr < 4; rr++) {
            int rl = tr + rr * 8;
            float v = x[(r0 + rl) * INSIZE + k0 + tc];
            sm[rl][tc] = v;
            out[(r0 + rl) * OUTW + k0 + tc] = v;   // fused x copy
        }
        __syncthreads();
#pragma unroll
        for (int rr = 0; rr < 4; rr++) {
            int kl = tr + rr * 8;
            g_xT[(k0 + kl) * NROWS + r0 + tc] = sm[tc][kl];
        }
    } else {
        const int t2 = blockIdx.x - 256;
        const int k0 = (t2 & 15) * 32;
        const int c0 = (t2 >> 4) * 32;
#pragma unroll
        for (int rr = 0; rr < 4; rr++) {
            int cl = tr + rr * 8;
            sm[cl][tc] = W[(c0 + cl) * INSIZE + k0 + tc];
        }
        __syncthreads();
#pragma unroll
        for (int rr = 0; rr < 4; rr++) {
            int kl = tr + rr * 8;
            float v = sm[tc][kl];
            *(float2*)&g_Wdup[(k0 + kl) * (2 * MM) + 2 * (c0 + tc)] =
                make_float2(v, v);
        }
    }
}

// ---------------------------------------------------------------------------
// Kernel 1: GEMM partials with cp.async 3-stage pipeline.
// grid (16 m, 8 n, 4 ksplit) = 512 blocks, 256 threads, 64x64 tile,
// micro-tile 4 cols x 4 rows (2 packed row-pairs), packed FFMA2.
// Xs streams from g_xT (rows pre-paired), Wd from g_Wdup (cols pre-dup).
// ---------------------------------------------------------------------------
__global__ __launch_bounds__(256)
void gemm_kernel() {
    __shared__ __align__(16) float Xs[3][16][64];    // 12 KB
    __shared__ __align__(16) float Wd[3][16][128];   // 24 KB

    const int bm = blockIdx.x * 64;
    const int bn = blockIdx.y * 64;
    const int kbase = blockIdx.z * 128;
    const int tid = threadIdx.x;

    const int kr = tid >> 4, seg = tid & 15;     // copy mapping
    const int tx = tid & 15, ty = tid >> 4;      // compute mapping

    const float* xsrc = g_xT + (kbase + kr) * NROWS + bn + seg * 4;
    const float* wsrc = g_Wdup + (kbase + kr) * (2 * MM) + 2 * bm + seg * 8;

    ull a00 = 0, a01 = 0, a10 = 0, a11 = 0, a20 = 0, a21 = 0, a30 = 0, a31 = 0;

#define ISSUE(st) do {                                                        \
        const int _q = (st) % 3;                                              \
        CPA16(su32(&Xs[_q][kr][seg * 4]), xsrc + (st) * 16 * NROWS);          \
        CPA16(su32(&Wd[_q][kr][seg * 8]), wsrc + (st) * 16 * (2 * MM));       \
        CPA16(su32(&Wd[_q][kr][seg * 8 + 4]),                                 \
              wsrc + (st) * 16 * (2 * MM) + 4);                               \
    } while (0)

    ISSUE(0); CPA_COMMIT();
    ISSUE(1); CPA_COMMIT();

    for (int st = 0; st < 8; st++) {
        CPA_WAIT1();
        __syncthreads();
        if (st < 6) ISSUE(st + 2);
        CPA_COMMIT();

        const int q = st % 3;
#pragma unroll
        for (int kk = 0; kk < 16; kk++) {
            ulonglong2 xp = *(const ulonglong2*)&Xs[q][kk][4 * ty];  // (r0,r1),(r2,r3)
            ulonglong2 w0 = *(const ulonglong2*)&Wd[q][kk][8 * tx];  // (c0,c0),(c1,c1)
            ulonglong2 w1 = *(const ulonglong2*)&Wd[q][kk][8 * tx + 4];
            a00 = fmaf32x2(w0.x, xp.x, a00);
            a01 = fmaf32x2(w0.x, xp.y, a01);
            a10 = fmaf32x2(w0.y, xp.x, a10);
            a11 = fmaf32x2(w0.y, xp.y, a11);
            a20 = fmaf32x2(w1.x, xp.x, a20);
            a21 = fmaf32x2(w1.x, xp.y, a21);
            a30 = fmaf32x2(w1.y, xp.x, a30);
            a31 = fmaf32x2(w1.y, xp.y, a31);
        }
    }
#undef ISSUE

    // epilogue: K-major partial store
    const int col = bm + 4 * tx;
    float* dst = g_P + blockIdx.z * PART + (col >> 4) * (NROWS * DD) + (col & 15);
    const int row0 = bn + 4 * ty;
    float4 o;
    o.x = lo32(a00); o.y = lo32(a10); o.z = lo32(a20); o.w = lo32(a30);
    *(float4*)&dst[(row0 + 0) * DD] = o;
    o.x = hi32(a00); o.y = hi32(a10); o.z = hi32(a20); o.w = hi32(a30);
    *(float4*)&dst[(row0 + 1) * DD] = o;
    o.x = lo32(a01); o.y = lo32(a11); o.z = lo32(a21); o.w = lo32(a31);
    *(float4*)&dst[(row0 + 2) * DD] = o;
    o.x = hi32(a01); o.y = hi32(a11); o.z = hi32(a21); o.w = hi32(a31);
    *(float4*)&dst[(row0 + 3) * DD] = o;
}

// ---------------------------------------------------------------------------
// Kernel 2: g_feat = sum of 4 partials + bias (k-major). 512 blocks x 256.
// ---------------------------------------------------------------------------
__global__ __launch_bounds__(256)
void sumfeat_kernel(const float* __restrict__ b) {
    const int idx = blockIdx.x * 256 + threadIdx.x;     // float4 index
    const int kg = idx >> 11;
    const int q = idx & 3;
    float4 v0 = ((const float4*)g_P)[idx];
    float4 v1 = ((const float4*)(g_P + PART))[idx];
    float4 v2 = ((const float4*)(g_P + 2 * PART))[idx];
    float4 v3 = ((const float4*)(g_P + 3 * PART))[idx];
    float4 bb = *(const float4*)&b[kg * DD + q * 4];
    float4 o;
    o.x = v0.x + v1.x + v2.x + v3.x + bb.x;
    o.y = v0.y + v1.y + v2.y + v3.y + bb.y;
    o.z = v0.z + v1.z + v2.z + v3.z + bb.z;
    o.w = v0.w + v1.w + v2.w + v3.w + bb.w;
    ((float4*)g_feat)[idx] = o;
}

// ---------------------------------------------------------------------------
// Kernel 3: symmetric pairwise, merged tile-rows. grid (64 k, 8 a), 256 thr.
// Block (k,a): loops tiles b=a..7. ti accumulated in registers across all
// tiles; tj per off-diagonal tile via sE + warp-shfl column reduce.
// Slots: tj -> g_part[a], ti -> g_part[7].
// ---------------------------------------------------------------------------
__global__ __launch_bounds__(256)
void pairwise_kernel() {
    __shared__ __align__(16) ull sA[T * 8];       // +tile a (4 KB)
    __shared__ __align__(16) ull sB[T * 8];       // -tile b (4 KB)
    __shared__ float sE[2 * T * 33];              // e-matrix (16.9 KB)
    __shared__ float sTot[8][32];

    const int k = blockIdx.x;
    const int a = blockIdx.y;
    const int tid = threadIdx.x;
    const int lane = tid & 31, w = tid >> 5;
    const int h = w >> 2, s = w & 3;
    const int iL = h * 32 + lane;

    const float4* feat4 = (const float4*)(g_feat + k * (NROWS * DD));

    // stripe a -> sA (positive)
    {
        int row = tid >> 2, q = tid & 3;
        float4 v = feat4[(a * T + row) * 4 + q];
        ((float2*)sA)[row * 8 + q * 2]     = make_float2(v.x, v.y);
        ((float2*)sA)[row * 8 + q * 2 + 1] = make_float2(v.z, v.w);
    }
    __syncthreads();

    ull fi[8];
    {
        const ulonglong2* p = (const ulonglong2*)&sA[iL * 8];
        ulonglong2 f0 = p[0], f1 = p[1], f2 = p[2], f3 = p[3];
        fi[0] = f0.x; fi[1] = f0.y; fi[2] = f1.x; fi[3] = f1.y;
        fi[4] = f2.x; fi[5] = f2.y; fi[6] = f3.x; fi[7] = f3.y;
    }

    const ull ABSM = 0x7fffffff7fffffffULL;
    float ti = 0.f;

    for (int bt = a; bt < 8; bt++) {
        // sB = -tile bt
        {
            int row = tid >> 2, q = tid & 3;
            float4 v = feat4[(bt * T + row) * 4 + q];
            ((float2*)sB)[row * 8 + q * 2]     = make_float2(-v.x, -v.y);
            ((float2*)sB)[row * 8 + q * 2 + 1] = make_float2(-v.z, -v.w);
        }
        __syncthreads();

        const bool off = (bt > a);
        const int jb = s * 16;
#pragma unroll 4
        for (int jj = 0; jj < 16; jj++) {
            const int j = jb + jj;
            const ulonglong2* row = (const ulonglong2*)&sB[j * 8];
            ulonglong2 q0 = row[0], q1 = row[1], q2 = row[2], q3 = row[3];
            ull d0 = addf32x2(fi[0], q0.x) & ABSM;
            ull d1 = addf32x2(fi[1], q0.y) & ABSM;
            ull d2 = addf32x2(fi[2], q1.x) & ABSM;
            ull d3 = addf32x2(fi[3], q1.y) & ABSM;
            ull d4 = addf32x2(fi[4], q2.x) & ABSM;
            ull d5 = addf32x2(fi[5], q2.y) & ABSM;
            ull d6 = addf32x2(fi[6], q3.x) & ABSM;
            ull d7 = addf32x2(fi[7], q3.y) & ABSM;
            ull sm = addf32x2(addf32x2(addf32x2(d0, d1), addf32x2(d2, d3)),
                              addf32x2(addf32x2(d4, d5), addf32x2(d6, d7)));
            float e = ex2f((lo32(sm) + hi32(sm)) * NLOG2E);
            ti += e;
            if (off) sE[h * (T * 33) + j * 33 + lane] = e;
        }
        __syncthreads();

        if (off) {
            // column reduce: warp w sums j = w*8..w*8+7 over 64 i
#pragma unroll
            for (int jj = 0; jj < 8; jj++) {
                const int j = w * 8 + jj;
                float v = sE[j * 33 + lane] + sE[T * 33 + j * 33 + lane];
                v += __shfl_xor_sync(0xffffffffu, v, 16);
                v += __shfl_xor_sync(0xffffffffu, v, 8);
                v += __shfl_xor_sync(0xffffffffu, v, 4);
                v += __shfl_xor_sync(0xffffffffu, v, 2);
                v += __shfl_xor_sync(0xffffffffu, v, 1);
                if (lane == 0)
                    g_part[a * PARTO + k * NROWS + bt * T + j] = v;
            }
        }
        __syncthreads();
    }

    sTot[w][lane] = ti;
    __syncthreads();
    if (tid < 64) {
        const int hh = tid >> 5, l = tid & 31;
        float t = sTot[hh * 4 + 0][l] + sTot[hh * 4 + 1][l] +
                  sTot[hh * 4 + 2][l] + sTot[hh * 4 + 3][l];
        g_part[7 * PARTO + k * NROWS + a * T + tid] = t;
    }
}

// ---------------------------------------------------------------------------
// Kernel 4: finalize o_b. row-tile r reads slot 7 (ti) + slots 0..r-1 (tj).
// ---------------------------------------------------------------------------
__global__ __launch_bounds__(512)
void final_kernel(float* __restrict__ out) {
    const int k = blockIdx.x;
    const int i = threadIdx.x;
    const int r = i >> 6;
    float t = g_part[7 * PARTO + k * NROWS + i] - 1.0f;   // remove diagonal
    for (int p = 0; p < r; p++)
        t += g_part[p * PARTO + k * NROWS + i];
    out[i * OUTW + INSIZE + k] = t;
}

// ---------------------------------------------------------------------------
extern "C" void kernel_launch(void* const* d_in, const int* in_sizes, int n_in,
                              void* d_out, int out_size) {
    const float* x = (const float*)d_in[0];   // [512,512]
    const float* W = (const float*)d_in[1];   // [1024,512]
    const float* b = (const float*)d_in[2];   // [1024]
    float* out = (float*)d_out;               // [512,576]

    prep_kernel<<<768, 256>>>(x, W, out);
    gemm_kernel<<<dim3(16, 8, 4), 256>>>();
    sumfeat_kernel<<<512, 256>>>(b);
    pairwise_kernel<<<dim3(KK, 8), 256>>>();
    final_kernel<<<KK, 512>>>(out);
}

// round 8
// speedup vs baseline: 1.3481x; 1.3481x over previous
#include <cuda_runtime.h>
#include <cstdint>

#define NROWS  512
#define INSIZE 512
#define KK     64
#define DD     16
#define MM     (KK * DD)        // 1024
#define OUTW   (INSIZE + KK)    // 576
#define BK     16
#define T      64               // pairwise tile size
#define PART   (NROWS * MM)     // one split-K partial, K-major [k][row][d]
#define PARTO  (NROWS * KK)     // one output-slot partial [k][i]
#define XPAD   68               // padded smem row (floats), 16B-aligned

typedef unsigned long long ull;

__device__ float g_P[2 * PART];          // split-K partials, K-major  4 MB
__device__ float g_feat[NROWS * MM];     // k-major feat (+bias)       2 MB
__device__ float g_part[8 * PARTO];      // output slots               1 MB

// ---------------------------------------------------------------------------
// helpers
// ---------------------------------------------------------------------------
__device__ __forceinline__ ull addf32x2(ull a, ull b) {
    ull r;
    asm("add.rn.f32x2 %0, %1, %2;" : "=l"(r) : "l"(a), "l"(b));
    return r;
}
__device__ __forceinline__ ull fmaf32x2(ull a, ull b, ull c) {
    ull r;
    asm("fma.rn.f32x2 %0, %1, %2, %3;" : "=l"(r) : "l"(a), "l"(b), "l"(c));
    return r;
}
__device__ __forceinline__ float lo32(ull v) {
    return __uint_as_float((unsigned int)v);
}
__device__ __forceinline__ float hi32(ull v) {
    return __uint_as_float((unsigned int)(v >> 32));
}
__device__ __forceinline__ float ex2f(float v) {
    float r;
    asm("ex2.approx.f32 %0, %1;" : "=f"(r) : "f"(v));
    return r;
}

#define NLOG2E (-1.4426950408889634f)

// ---------------------------------------------------------------------------
// Kernel 1: split-K(2) GEMM partials. grid (16 m, 16 n, 2) = 512 blocks,
// 128 threads, 64m x 32n tile, 4x4 micro-tile packed FFMA2, double-buffered.
// Same inner instruction stream as the proven R5 kernel; only the grid/tile
// shape changed for SM load balance (1.73 -> 3.46 blocks/SM).
// ---------------------------------------------------------------------------
__global__ __launch_bounds__(128)
void gemm_kernel(const float* __restrict__ x, const float* __restrict__ W) {
    __shared__ __align__(16) float XsD[2][BK][XPAD];  // dup x rows (64 used)
    __shared__ __align__(16) float Ws [2][BK][XPAD];  // W cols (64 used)

    const int bm = blockIdx.x * 64;       // feat col tile
    const int bn = blockIdx.y * 32;       // row tile
    const int kbase = blockIdx.z * 256;   // k half
    float* dst = g_P + blockIdx.z * PART;

    const int tid = threadIdx.x;
    // x loader: 1 float4 (32 rows x 4 quads = 128)
    const int xr = tid >> 2;              // 0..31
    const int xc = (tid & 3) * 4;         // 0,4,8,12
    // W loader: 2 float4 (64 cols x 4 quads = 256)
    // compute mapping
    const int tx = tid & 15;              // cols 4tx..4tx+3
    const int ty = tid >> 4;              // 0..7 -> rows 4ty..4ty+3

    const float* xg = &x[(bn + xr) * INSIZE + kbase + xc];

    ull acc[4][2];
#pragma unroll
    for (int r = 0; r < 4; r++) { acc[r][0] = 0ULL; acc[r][1] = 0ULL; }

    int buf = 0;
    {
        float4 xv = *(const float4*)xg;
        float xa[4] = {xv.x, xv.y, xv.z, xv.w};
#pragma unroll
        for (int q = 0; q < 4; q++)
            *(float2*)&XsD[buf][xc + q][2 * xr] = make_float2(xa[q], xa[q]);
#pragma unroll
        for (int t = 0; t < 2; t++) {
            int idx = tid + t * 128;
            int wc = idx >> 2, wl = (idx & 3) * 4;
            float4 wv = *(const float4*)&W[(bm + wc) * INSIZE + kbase + wl];
            float wa[4] = {wv.x, wv.y, wv.z, wv.w};
#pragma unroll
            for (int q = 0; q < 4; q++) Ws[buf][wl + q][wc] = wa[q];
        }
    }
    __syncthreads();

    for (int step = 1; step <= 16; step++) {
        const bool more = (step < 16);
        float4 xv2, wv2a, wv2b;
        if (more) {
            xv2 = *(const float4*)(xg + step * BK);
            int i0 = tid, i1 = tid + 128;
            wv2a = *(const float4*)&W[(bm + (i0 >> 2)) * INSIZE + kbase +
                                      step * BK + (i0 & 3) * 4];
            wv2b = *(const float4*)&W[(bm + (i1 >> 2)) * INSIZE + kbase +
                                      step * BK + (i1 & 3) * 4];
        }

#pragma unroll
        for (int kk = 0; kk < BK; kk++) {
            ulonglong2 xp = *(const ulonglong2*)&XsD[buf][kk][8 * ty];      // (r0,r0),(r1,r1)
            ulonglong2 xq = *(const ulonglong2*)&XsD[buf][kk][8 * ty + 4];  // (r2,r2),(r3,r3)
            ulonglong2 wp = *(const ulonglong2*)&Ws [buf][kk][4 * tx];
            acc[0][0] = fmaf32x2(xp.x, wp.x, acc[0][0]);
            acc[0][1] = fmaf32x2(xp.x, wp.y, acc[0][1]);
            acc[1][0] = fmaf32x2(xp.y, wp.x, acc[1][0]);
            acc[1][1] = fmaf32x2(xp.y, wp.y, acc[1][1]);
            acc[2][0] = fmaf32x2(xq.x, wp.x, acc[2][0]);
            acc[2][1] = fmaf32x2(xq.x, wp.y, acc[2][1]);
            acc[3][0] = fmaf32x2(xq.y, wp.x, acc[3][0]);
            acc[3][1] = fmaf32x2(xq.y, wp.y, acc[3][1]);
        }

        if (more) {
            buf ^= 1;
            float xa[4] = {xv2.x, xv2.y, xv2.z, xv2.w};
#pragma unroll
            for (int q = 0; q < 4; q++)
                *(float2*)&XsD[buf][xc + q][2 * xr] = make_float2(xa[q], xa[q]);
            float wa[4] = {wv2a.x, wv2a.y, wv2a.z, wv2a.w};
            float wb[4] = {wv2b.x, wv2b.y, wv2b.z, wv2b.w};
            int c0 = tid >> 2, l0 = (tid & 3) * 4;
            int c1 = (tid + 128) >> 2, l1 = (tid & 3) * 4;
#pragma unroll
            for (int q = 0; q < 4; q++) {
                Ws[buf][l0 + q][c0] = wa[q];
                Ws[buf][l1 + q][c1] = wb[q];
            }
            __syncthreads();
        }
    }

    // epilogue: K-major partial store
    const int col = bm + 4 * tx;
    float* base = dst + (col >> 4) * (NROWS * DD) + (col & 15);
#pragma unroll
    for (int r = 0; r < 4; r++) {
        float4 o;
        o.x = lo32(acc[r][0]);
        o.y = hi32(acc[r][0]);
        o.z = lo32(acc[r][1]);
        o.w = hi32(acc[r][1]);
        *(float4*)&base[(bn + 4 * ty + r) * DD] = o;
    }
}

// ---------------------------------------------------------------------------
// Kernel 2: g_feat = g_P[0] + g_P[1] + bias (k-major). 512 blocks x 256.
// ---------------------------------------------------------------------------
__global__ __launch_bounds__(256)
void sumfeat_kernel(const float* __restrict__ b) {
    const int idx = blockIdx.x * 256 + threadIdx.x;     // float4 index
    const int kg = idx >> 11;                           // 2048 float4 per k
    const int q = idx & 3;
    float4 v0 = ((const float4*)g_P)[idx];
    float4 v1 = ((const float4*)(g_P + PART))[idx];
    float4 bb = *(const float4*)&b[kg * DD + q * 4];
    float4 o;
    o.x = v0.x + v1.x + bb.x;
    o.y = v0.y + v1.y + bb.y;
    o.z = v0.z + v1.z + bb.z;
    o.w = v0.w + v1.w + bb.w;
    ((float4*)g_feat)[idx] = o;
}

// ---------------------------------------------------------------------------
// Kernel 3: symmetric pairwise L1+exp, 64x64 tile-pairs, balanced units.
// grid (64 k, 36 units), 256 threads. unit<8: diagonal; else (a<bt) pair.
// ti per-lane registers; tj via sE + 8-warp shfl column reduce.
// Slots: ti -> g_part[bt], tj -> g_part[a].
// ---------------------------------------------------------------------------
__global__ __launch_bounds__(256)
void pairwise_kernel() {
    __shared__ __align__(16) ull sA[T * 8];        // +tile a (4 KB)
    __shared__ __align__(16) ull sB[T * 8];        // -tile b (4 KB)
    __shared__ float sE[2 * T * 33];               // e-matrix
    __shared__ float sTot[8][32];

    const int k = blockIdx.x;
    int u = blockIdx.y;
    int a, bt;
    if (u < 8) { a = u; bt = u; }
    else {
        int v = u - 8;
        a = 0;
        while (v >= 7 - a) { v -= 7 - a; a++; }
        bt = a + 1 + v;
    }
    const bool diag = (a == bt);
    const int tid = threadIdx.x;
    const int lane = tid & 31, w = tid >> 5;
    const int h = w >> 2, s = w & 3;
    const int iL = h * 32 + lane;

    const float4* feat4 = (const float4*)(g_feat + k * (NROWS * DD));

    // stripe loads: 1 float4 per thread per stripe
    {
        int row = tid >> 2, q = tid & 3;
        float4 v = feat4[(a * T + row) * 4 + q];
        ((float2*)sA)[row * 8 + q * 2]     = make_float2(v.x, v.y);
        ((float2*)sA)[row * 8 + q * 2 + 1] = make_float2(v.z, v.w);
        float4 u4 = feat4[(bt * T + row) * 4 + q];
        ((float2*)sB)[row * 8 + q * 2]     = make_float2(-u4.x, -u4.y);
        ((float2*)sB)[row * 8 + q * 2 + 1] = make_float2(-u4.z, -u4.w);
    }
    __syncthreads();

    ull fi[8];
    {
        const ulonglong2* p = (const ulonglong2*)&sA[iL * 8];
        ulonglong2 f0 = p[0], f1 = p[1], f2 = p[2], f3 = p[3];
        fi[0] = f0.x; fi[1] = f0.y; fi[2] = f1.x; fi[3] = f1.y;
        fi[4] = f2.x; fi[5] = f2.y; fi[6] = f3.x; fi[7] = f3.y;
    }

    const ull ABSM = 0x7fffffff7fffffffULL;
    float ti = 0.f;
    const int jb = s * 16;

#pragma unroll 4
    for (int jj = 0; jj < 16; jj++) {
        const int j = jb + jj;
        const ulonglong2* row = (const ulonglong2*)&sB[j * 8];
        ulonglong2 q0 = row[0], q1 = row[1], q2 = row[2], q3 = row[3];
        ull d0 = addf32x2(fi[0], q0.x) & ABSM;
        ull d1 = addf32x2(fi[1], q0.y) & ABSM;
        ull d2 = addf32x2(fi[2], q1.x) & ABSM;
        ull d3 = addf32x2(fi[3], q1.y) & ABSM;
        ull d4 = addf32x2(fi[4], q2.x) & ABSM;
        ull d5 = addf32x2(fi[5], q2.y) & ABSM;
        ull d6 = addf32x2(fi[6], q3.x) & ABSM;
        ull d7 = addf32x2(fi[7], q3.y) & ABSM;
        ull sm = addf32x2(addf32x2(addf32x2(d0, d1), addf32x2(d2, d3)),
                          addf32x2(addf32x2(d4, d5), addf32x2(d6, d7)));
        float e = ex2f((lo32(sm) + hi32(sm)) * NLOG2E);
        ti += e;
        if (!diag) sE[h * (T * 33) + j * 33 + lane] = e;
    }

    sTot[w][lane] = ti;
    __syncthreads();

    if (tid < 64) {
        const int hh = tid >> 5, l = tid & 31;
        float t = sTot[hh * 4 + 0][l] + sTot[hh * 4 + 1][l] +
                  sTot[hh * 4 + 2][l] + sTot[hh * 4 + 3][l];
        g_part[bt * PARTO + k * NROWS + a * T + tid] = t;
    }

    if (!diag) {
        // column reduce: warp w sums columns j = w*8..w*8+7 over 64 i
#pragma unroll
        for (int jj = 0; jj < 8; jj++) {
            const int j = w * 8 + jj;
            float v = sE[j * 33 + lane] + sE[T * 33 + j * 33 + lane];
            v += __shfl_xor_sync(0xffffffffu, v, 16);
            v += __shfl_xor_sync(0xffffffffu, v, 8);
            v += __shfl_xor_sync(0xffffffffu, v, 4);
            v += __shfl_xor_sync(0xffffffffu, v, 2);
            v += __shfl_xor_sync(0xffffffffu, v, 1);
            if (lane == 0)
                g_part[a * PARTO + k * NROWS + bt * T + j] = v;
        }
    }
}

// ---------------------------------------------------------------------------
// Kernel 4: finalize o_b + x copy. grid 64, 512 threads.
// ---------------------------------------------------------------------------
__global__ __launch_bounds__(512)
void final_kernel(const float* __restrict__ x, float* __restrict__ out) {
    const int k = blockIdx.x;
    const int i = threadIdx.x;

    float t = -1.0f;
#pragma unroll
    for (int p = 0; p < 8; p++) t += g_part[p * PARTO + k * NROWS + i];
    out[i * OUTW + INSIZE + k] = t;

    const float4* xin = (const float4*)x;
    float4* o4 = (float4*)out;
#pragma unroll
    for (int v = 0; v < 2; v++) {
        int idx = (k * 512 + i) * 2 + v;          // 0..65535
        o4[(idx >> 7) * 144 + (idx & 127)] = xin[idx];
    }
}

// ---------------------------------------------------------------------------
extern "C" void kernel_launch(void* const* d_in, const int* in_sizes, int n_in,
                              void* d_out, int out_size) {
    const float* x = (const float*)d_in[0];   // [512,512]
    const float* W = (const float*)d_in[1];   // [1024,512]
    const float* b = (const float*)d_in[2];   // [1024]
    float* out = (float*)d_out;               // [512,576]

    gemm_kernel<<<dim3(16, 16, 2), 128>>>(x, W);
    sumfeat_kernel<<<512, 256>>>(b);
    pairwise_kernel<<<dim3(KK, 36), 256>>>();
    final_kernel<<<KK, 512>>>(x, out);
}

// round 9
// speedup vs baseline: 1.4323x; 1.0625x over previous
#include <cuda_runtime.h>
#include <cstdint>

#define NROWS  512
#define INSIZE 512
#define KK     64
#define DD     16
#define MM     (KK * DD)        // 1024
#define OUTW   (INSIZE + KK)    // 576
#define BK     16
#define T      64               // pairwise tile size
#define PART   (NROWS * MM)     // one split-K partial, K-major [k][row][d]
#define PARTO  (NROWS * KK)     // one output-slot partial [k][i]
#define XPAD   68

typedef unsigned long long ull;

__device__ float g_P[2 * PART];          // split-K partials, K-major (bias in P0)
__device__ float g_part[8 * PARTO];      // output slots

// pairing tables: block u handles units (a, bt0) and, if n==2, (a, bt0+1)
__constant__ int c_a [20] = {0,0,0,0, 1,1,1,1, 2,2,2, 3,3,3, 4,4, 5,5, 6, 7};
__constant__ int c_b0[20] = {0,2,4,6, 1,3,5,7, 2,4,6, 3,5,7, 4,6, 5,7, 6, 7};
__constant__ int c_n [20] = {2,2,2,2, 2,2,2,1, 2,2,2, 2,2,1, 2,2, 2,1, 2, 1};

// ---------------------------------------------------------------------------
// helpers
// ---------------------------------------------------------------------------
__device__ __forceinline__ ull addf32x2(ull a, ull b) {
    ull r;
    asm("add.rn.f32x2 %0, %1, %2;" : "=l"(r) : "l"(a), "l"(b));
    return r;
}
__device__ __forceinline__ ull fmaf32x2(ull a, ull b, ull c) {
    ull r;
    asm("fma.rn.f32x2 %0, %1, %2, %3;" : "=l"(r) : "l"(a), "l"(b), "l"(c));
    return r;
}
__device__ __forceinline__ float lo32(ull v) {
    return __uint_as_float((unsigned int)v);
}
__device__ __forceinline__ float hi32(ull v) {
    return __uint_as_float((unsigned int)(v >> 32));
}
__device__ __forceinline__ float ex2f(float v) {
    float r;
    asm("ex2.approx.f32 %0, %1;" : "=f"(r) : "f"(v));
    return r;
}

#define NLOG2E (-1.4426950408889634f)

// ---------------------------------------------------------------------------
// Kernel 1: split-K(2) GEMM partials (R8 config: 64m x 32n, 128 thr,
// grid (16,16,2)). Bias folded into the z==0 epilogue.
// ---------------------------------------------------------------------------
__global__ __launch_bounds__(128)
void gemm_kernel(const float* __restrict__ x, const float* __restrict__ W,
                 const float* __restrict__ b) {
    __shared__ __align__(16) float XsD[2][BK][XPAD];
    __shared__ __align__(16) float Ws [2][BK][XPAD];

    const int bm = blockIdx.x * 64;
    const int bn = blockIdx.y * 32;
    const int kbase = blockIdx.z * 256;
    float* dst = g_P + blockIdx.z * PART;

    const int tid = threadIdx.x;
    const int xr = tid >> 2;
    const int xc = (tid & 3) * 4;
    const int tx = tid & 15;
    const int ty = tid >> 4;

    const float* xg = &x[(bn + xr) * INSIZE + kbase + xc];

    ull acc[4][2];
#pragma unroll
    for (int r = 0; r < 4; r++) { acc[r][0] = 0ULL; acc[r][1] = 0ULL; }

    int buf = 0;
    {
        float4 xv = *(const float4*)xg;
        float xa[4] = {xv.x, xv.y, xv.z, xv.w};
#pragma unroll
        for (int q = 0; q < 4; q++)
            *(float2*)&XsD[buf][xc + q][2 * xr] = make_float2(xa[q], xa[q]);
#pragma unroll
        for (int t = 0; t < 2; t++) {
            int idx = tid + t * 128;
            int wc = idx >> 2, wl = (idx & 3) * 4;
            float4 wv = *(const float4*)&W[(bm + wc) * INSIZE + kbase + wl];
            float wa[4] = {wv.x, wv.y, wv.z, wv.w};
#pragma unroll
            for (int q = 0; q < 4; q++) Ws[buf][wl + q][wc] = wa[q];
        }
    }
    __syncthreads();

    for (int step = 1; step <= 16; step++) {
        const bool more = (step < 16);
        float4 xv2, wv2a, wv2b;
        if (more) {
            xv2 = *(const float4*)(xg + step * BK);
            int i0 = tid, i1 = tid + 128;
            wv2a = *(const float4*)&W[(bm + (i0 >> 2)) * INSIZE + kbase +
                                      step * BK + (i0 & 3) * 4];
            wv2b = *(const float4*)&W[(bm + (i1 >> 2)) * INSIZE + kbase +
                                      step * BK + (i1 & 3) * 4];
        }

#pragma unroll
        for (int kk = 0; kk < BK; kk++) {
            ulonglong2 xp = *(const ulonglong2*)&XsD[buf][kk][8 * ty];
            ulonglong2 xq = *(const ulonglong2*)&XsD[buf][kk][8 * ty + 4];
            ulonglong2 wp = *(const ulonglong2*)&Ws [buf][kk][4 * tx];
            acc[0][0] = fmaf32x2(xp.x, wp.x, acc[0][0]);
            acc[0][1] = fmaf32x2(xp.x, wp.y, acc[0][1]);
            acc[1][0] = fmaf32x2(xp.y, wp.x, acc[1][0]);
            acc[1][1] = fmaf32x2(xp.y, wp.y, acc[1][1]);
            acc[2][0] = fmaf32x2(xq.x, wp.x, acc[2][0]);
            acc[2][1] = fmaf32x2(xq.x, wp.y, acc[2][1]);
            acc[3][0] = fmaf32x2(xq.y, wp.x, acc[3][0]);
            acc[3][1] = fmaf32x2(xq.y, wp.y, acc[3][1]);
        }

        if (more) {
            buf ^= 1;
            float xa[4] = {xv2.x, xv2.y, xv2.z, xv2.w};
#pragma unroll
            for (int q = 0; q < 4; q++)
                *(float2*)&XsD[buf][xc + q][2 * xr] = make_float2(xa[q], xa[q]);
            float wa[4] = {wv2a.x, wv2a.y, wv2a.z, wv2a.w};
            float wb[4] = {wv2b.x, wv2b.y, wv2b.z, wv2b.w};
            int c0 = tid >> 2, l0 = (tid & 3) * 4;
            int c1 = (tid + 128) >> 2;
#pragma unroll
            for (int q = 0; q < 4; q++) {
                Ws[buf][l0 + q][c0] = wa[q];
                Ws[buf][l0 + q][c1] = wb[q];
            }
            __syncthreads();
        }
    }

    // epilogue: bias only in z==0 partial
    float4 bv = make_float4(0.f, 0.f, 0.f, 0.f);
    if (blockIdx.z == 0) bv = *(const float4*)&b[bm + 4 * tx];

    const int col = bm + 4 * tx;
    float* base = dst + (col >> 4) * (NROWS * DD) + (col & 15);
#pragma unroll
    for (int r = 0; r < 4; r++) {
        float4 o;
        o.x = lo32(acc[r][0]) + bv.x;
        o.y = hi32(acc[r][0]) + bv.y;
        o.z = lo32(acc[r][1]) + bv.z;
        o.w = hi32(acc[r][1]) + bv.w;
        *(float4*)&base[(bn + 4 * ty + r) * DD] = o;
    }
}

// ---------------------------------------------------------------------------
// Pairwise compute body: 16 rows of -tile in sBb against fi, accumulate ti,
// optionally record e-matrix into sE bank.
// ---------------------------------------------------------------------------
__device__ __forceinline__ float pair_body(const ull* __restrict__ sBb,
                                           const ull* fi, float* __restrict__ eB,
                                           int jb, int h, int lane, bool rec) {
    const ull ABSM = 0x7fffffff7fffffffULL;
    float ti = 0.f;
#pragma unroll 4
    for (int jj = 0; jj < 16; jj++) {
        const int j = jb + jj;
        const ulonglong2* row = (const ulonglong2*)&sBb[j * 8];
        ulonglong2 q0 = row[0], q1 = row[1], q2 = row[2], q3 = row[3];
        ull d0 = addf32x2(fi[0], q0.x) & ABSM;
        ull d1 = addf32x2(fi[1], q0.y) & ABSM;
        ull d2 = addf32x2(fi[2], q1.x) & ABSM;
        ull d3 = addf32x2(fi[3], q1.y) & ABSM;
        ull d4 = addf32x2(fi[4], q2.x) & ABSM;
        ull d5 = addf32x2(fi[5], q2.y) & ABSM;
        ull d6 = addf32x2(fi[6], q3.x) & ABSM;
        ull d7 = addf32x2(fi[7], q3.y) & ABSM;
        ull sm = addf32x2(addf32x2(addf32x2(d0, d1), addf32x2(d2, d3)),
                          addf32x2(addf32x2(d4, d5), addf32x2(d6, d7)));
        float e = ex2f((lo32(sm) + hi32(sm)) * NLOG2E);
        ti += e;
        if (rec) eB[h * (T * 32) + j * 32 + lane] = e;
    }
    return ti;
}

// ---------------------------------------------------------------------------
// Kernel 2: symmetric pairwise, paired units. grid (64 k, 20), 256 thr.
// Block u: units (a,bt0) and (a,bt0+1) if c_n==2. sA/fi shared; unit-1
// stripe prefetched into registers before unit-0 compute (latency hidden).
// ti -> g_part[bt], tj -> g_part[a] (disjoint, deterministic).
// ---------------------------------------------------------------------------
__global__ __launch_bounds__(256)
void pairwise_kernel() {
    __shared__ __align__(16) ull sA[T * 8];        // +tile a
    __shared__ __align__(16) ull sB[2][T * 8];     // -tiles (2 banks)
    __shared__ float sE[2][2 * T * 32];            // e-matrix (2 banks, 32KB)
    __shared__ float sTot[2][8][32];

    const int k  = blockIdx.x;
    const int u  = blockIdx.y;
    const int a  = c_a[u];
    const int bt0 = c_b0[u];
    const int n  = c_n[u];
    const int bt1 = bt0 + 1;

    const int tid = threadIdx.x;
    const int lane = tid & 31, w = tid >> 5;
    const int h = w >> 2, s = w & 3;
    const int iL = h * 32 + lane;
    const int jb = s * 16;

    const float* P0 = g_P + k * (NROWS * DD);
    const float* P1 = P0 + PART;
    const int row = tid >> 2, q4 = (tid & 3) * 4;

    // stripe a (+) and bt0 (-)
    {
        float4 v0 = *(const float4*)&P0[(a * T + row) * DD + q4];
        float4 v1 = *(const float4*)&P1[(a * T + row) * DD + q4];
        ((float2*)sA)[row * 8 + (q4 >> 1)]     = make_float2(v0.x + v1.x, v0.y + v1.y);
        ((float2*)sA)[row * 8 + (q4 >> 1) + 1] = make_float2(v0.z + v1.z, v0.w + v1.w);
        float4 u0 = *(const float4*)&P0[(bt0 * T + row) * DD + q4];
        float4 u1 = *(const float4*)&P1[(bt0 * T + row) * DD + q4];
        ((float2*)sB[0])[row * 8 + (q4 >> 1)]     = make_float2(-(u0.x + u1.x), -(u0.y + u1.y));
        ((float2*)sB[0])[row * 8 + (q4 >> 1) + 1] = make_float2(-(u0.z + u1.z), -(u0.w + u1.w));
    }

    // prefetch unit-1 stripe into registers (latency hidden by unit-0 compute)
    float4 w0, w1;
    if (n == 2) {
        w0 = *(const float4*)&P0[(bt1 * T + row) * DD + q4];
        w1 = *(const float4*)&P1[(bt1 * T + row) * DD + q4];
    }
    __syncthreads();

    ull fi[8];
    {
        const ulonglong2* p = (const ulonglong2*)&sA[iL * 8];
        ulonglong2 f0 = p[0], f1 = p[1], f2 = p[2], f3 = p[3];
        fi[0] = f0.x; fi[1] = f0.y; fi[2] = f1.x; fi[3] = f1.y;
        fi[4] = f2.x; fi[5] = f2.y; fi[6] = f3.x; fi[7] = f3.y;
    }

    const bool diag0 = (a == bt0);
    float ti0 = pair_body(sB[0], fi, sE[0], jb, h, lane, !diag0);
    sTot[0][w][lane] = ti0;

    if (n == 2) {
        ((float2*)sB[1])[row * 8 + (q4 >> 1)]     = make_float2(-(w0.x + w1.x), -(w0.y + w1.y));
        ((float2*)sB[1])[row * 8 + (q4 >> 1) + 1] = make_float2(-(w0.z + w1.z), -(w0.w + w1.w));
    }
    __syncthreads();     // publishes sE[0], sTot[0], sB[1]

    // unit-0 tj reduce (bank 0)
    if (!diag0) {
#pragma unroll
        for (int jj = 0; jj < 8; jj++) {
            const int j = w * 8 + jj;
            float v = sE[0][j * 32 + lane] + sE[0][T * 32 + j * 32 + lane];
            v += __shfl_xor_sync(0xffffffffu, v, 16);
            v += __shfl_xor_sync(0xffffffffu, v, 8);
            v += __shfl_xor_sync(0xffffffffu, v, 4);
            v += __shfl_xor_sync(0xffffffffu, v, 2);
            v += __shfl_xor_sync(0xffffffffu, v, 1);
            if (lane == 0)
                g_part[a * PARTO + k * NROWS + bt0 * T + j] = v;
        }
    }

    if (n == 2) {
        // unit 1 is always off-diagonal (bt1 > a)
        float ti1 = pair_body(sB[1], fi, sE[1], jb, h, lane, true);
        sTot[1][w][lane] = ti1;
    }
    __syncthreads();     // publishes sE[1], sTot[1]

    if (n == 2) {
#pragma unroll
        for (int jj = 0; jj < 8; jj++) {
            const int j = w * 8 + jj;
            float v = sE[1][j * 32 + lane] + sE[1][T * 32 + j * 32 + lane];
            v += __shfl_xor_sync(0xffffffffu, v, 16);
            v += __shfl_xor_sync(0xffffffffu, v, 8);
            v += __shfl_xor_sync(0xffffffffu, v, 4);
            v += __shfl_xor_sync(0xffffffffu, v, 2);
            v += __shfl_xor_sync(0xffffffffu, v, 1);
            if (lane == 0)
                g_part[a * PARTO + k * NROWS + bt1 * T + j] = v;
        }
    }

    // ti reductions: tid<64 -> unit 0, tid in [64,128) -> unit 1
    if (tid < 64) {
        const int hh = tid >> 5, l = tid & 31;
        float t = sTot[0][hh * 4 + 0][l] + sTot[0][hh * 4 + 1][l] +
                  sTot[0][hh * 4 + 2][l] + sTot[0][hh * 4 + 3][l];
        g_part[bt0 * PARTO + k * NROWS + a * T + tid] = t;
    } else if (n == 2 && tid < 128) {
        const int t2 = tid - 64;
        const int hh = t2 >> 5, l = t2 & 31;
        float t = sTot[1][hh * 4 + 0][l] + sTot[1][hh * 4 + 1][l] +
                  sTot[1][hh * 4 + 2][l] + sTot[1][hh * 4 + 3][l];
        g_part[bt1 * PARTO + k * NROWS + a * T + t2] = t;
    }
}

// ---------------------------------------------------------------------------
// Kernel 3: finalize o_b + x copy. grid 256 x 256 (65536 threads).
// ---------------------------------------------------------------------------
__global__ __launch_bounds__(256)
void final_kernel(const float* __restrict__ x, float* __restrict__ out) {
    const int g = blockIdx.x * 256 + threadIdx.x;    // 0..65535

    // x copy: one float4 each
    ((float4*)out)[(g >> 7) * 144 + (g & 127)] = ((const float4*)x)[g];

    if (g < NROWS * KK) {
        const int k = g >> 9;       // 0..63
        const int i = g & 511;      // coalesced g_part reads
        float t = -1.0f;
#pragma unroll
        for (int p = 0; p < 8; p++) t += g_part[p * PARTO + k * NROWS + i];
        out[i * OUTW + INSIZE + k] = t;
    }
}

// ---------------------------------------------------------------------------
extern "C" void kernel_launch(void* const* d_in, const int* in_sizes, int n_in,
                              void* d_out, int out_size) {
    const float* x = (const float*)d_in[0];   // [512,512]
    const float* W = (const float*)d_in[1];   // [1024,512]
    const float* b = (const float*)d_in[2];   // [1024]
    float* out = (float*)d_out;               // [512,576]

    gemm_kernel<<<dim3(16, 16, 2), 128>>>(x, W, b);
    pairwise_kernel<<<dim3(KK, 20), 256>>>();
    final_kernel<<<256, 256>>>(x, out);
}

// round 10
// speedup vs baseline: 1.5458x; 1.0792x over previous
#include <cuda_runtime.h>
#include <cstdint>

#define NROWS  512
#define INSIZE 512
#define KK     64
#define DD     16
#define MM     (KK * DD)        // 1024
#define OUTW   (INSIZE + KK)    // 576
#define BK     16
#define T      64
#define PART   (NROWS * MM)     // one split-K partial, K-major [k][row][d]
#define PARTO  (NROWS * KK)     // one output-slot partial [k][i]

typedef unsigned long long ull;

__device__ float g_P[4 * PART];          // split-K partials, K-major  8 MB
__device__ float g_feat[NROWS * MM];     // k-major feat (+bias)       2 MB
__device__ float g_part[8 * PARTO];      // output slots               1 MB

// 36 tile-units: 8 diagonal + 28 upper-triangle
__constant__ int c_ua[36] = {0,1,2,3,4,5,6,7, 0,0,0,0,0,0,0, 1,1,1,1,1,1,
                             2,2,2,2,2, 3,3,3,3, 4,4,4, 5,5, 6};
__constant__ int c_ub[36] = {0,1,2,3,4,5,6,7, 1,2,3,4,5,6,7, 2,3,4,5,6,7,
                             3,4,5,6,7, 4,5,6,7, 5,6,7, 6,7, 7};

// ---------------------------------------------------------------------------
// helpers
// ---------------------------------------------------------------------------
__device__ __forceinline__ ull addf32x2(ull a, ull b) {
    ull r;
    asm("add.rn.f32x2 %0, %1, %2;" : "=l"(r) : "l"(a), "l"(b));
    return r;
}
__device__ __forceinline__ ull fmaf32x2(ull a, ull b, ull c) {
    ull r;
    asm("fma.rn.f32x2 %0, %1, %2, %3;" : "=l"(r) : "l"(a), "l"(b), "l"(c));
    return r;
}
__device__ __forceinline__ float lo32(ull v) {
    return __uint_as_float((unsigned int)v);
}
__device__ __forceinline__ float hi32(ull v) {
    return __uint_as_float((unsigned int)(v >> 32));
}
__device__ __forceinline__ float ex2f(float v) {
    float r;
    asm("ex2.approx.f32 %0, %1;" : "=f"(r) : "f"(v));
    return r;
}
__device__ __forceinline__ unsigned su32(const void* p) {
    return (unsigned)__cvta_generic_to_shared(p);
}
#define CPA16(dst, src) \
    asm volatile("cp.async.cg.shared.global [%0], [%1], 16;" :: "r"(dst), "l"(src))
#define CPA_COMMIT() asm volatile("cp.async.commit_group;")
#define CPA_WAIT0()  asm volatile("cp.async.wait_group 0;")

#define NLOG2E (-1.4426950408889634f)

// ---------------------------------------------------------------------------
// Kernel 1: split-K(4) GEMM partials, 8x8 micro-tile.
// grid (8 m, 8 n, 4 z), 128 threads, tile 128m x 64n.
// Per kk per thread: 2 LDS.128 (x pairs, broadcast) + 8 LDS.64 (W dup,
// strided cols tx+16c -> conflict-free) + 32 FFMA2. 1.5 smem-B/FMA.
// ---------------------------------------------------------------------------
__global__ __launch_bounds__(128)
void gemm_kernel(const float* __restrict__ x, const float* __restrict__ W) {
    __shared__ __align__(16) float Xs[2][BK][68];   // transposed x, padded
    __shared__ __align__(16) ull   Wd[2][BK][129];  // dup W cols, padded

    const int bm = blockIdx.x * 128;
    const int bn = blockIdx.y * 64;
    const int kz = blockIdx.z * 128;
    const int tid = threadIdx.x;
    const int tx = tid & 15, ty = tid >> 4;

    ull acc[4][8];
#pragma unroll
    for (int rp = 0; rp < 4; rp++)
#pragma unroll
        for (int c = 0; c < 8; c++) acc[rp][c] = 0ULL;

    float4 xs4[2], ws4[4];

#define GLOAD(step) do {                                                     \
    _Pragma("unroll")                                                        \
    for (int j = 0; j < 2; j++) {                                            \
        int idx = tid + j * 128; int row = idx >> 2, kq = idx & 3;           \
        xs4[j] = *(const float4*)&x[(bn + row) * INSIZE + kz +               \
                                    (step) * BK + kq * 4];                   \
    }                                                                        \
    _Pragma("unroll")                                                        \
    for (int j = 0; j < 4; j++) {                                            \
        int idx = tid + j * 128; int col = idx >> 2, kq = idx & 3;           \
        ws4[j] = *(const float4*)&W[(bm + col) * INSIZE + kz +               \
                                    (step) * BK + kq * 4];                   \
    }                                                                        \
} while (0)

#define SSTORE(bf) do {                                                      \
    _Pragma("unroll")                                                        \
    for (int j = 0; j < 2; j++) {                                            \
        int idx = tid + j * 128; int row = idx >> 2, kq = idx & 3;           \
        float v[4] = {xs4[j].x, xs4[j].y, xs4[j].z, xs4[j].w};               \
        _Pragma("unroll")                                                    \
        for (int jj = 0; jj < 4; jj++) Xs[bf][kq * 4 + jj][row] = v[jj];     \
    }                                                                        \
    _Pragma("unroll")                                                        \
    for (int j = 0; j < 4; j++) {                                            \
        int idx = tid + j * 128; int col = idx >> 2, kq = idx & 3;           \
        float v[4] = {ws4[j].x, ws4[j].y, ws4[j].z, ws4[j].w};               \
        _Pragma("unroll")                                                    \
        for (int jj = 0; jj < 4; jj++)                                       \
            *(float2*)&Wd[bf][kq * 4 + jj][col] = make_float2(v[jj], v[jj]); \
    }                                                                        \
} while (0)

    GLOAD(0); SSTORE(0); __syncthreads();
    int buf = 0;

    for (int step = 1; step <= 8; step++) {
        const bool more = (step < 8);
        if (more) GLOAD(step);

#pragma unroll
        for (int kk = 0; kk < BK; kk++) {
            ulonglong2 xp0 = *(const ulonglong2*)&Xs[buf][kk][8 * ty];
            ulonglong2 xp1 = *(const ulonglong2*)&Xs[buf][kk][8 * ty + 4];
            ull xr[4] = {xp0.x, xp0.y, xp1.x, xp1.y};
            ull wd[8];
#pragma unroll
            for (int c = 0; c < 8; c++) wd[c] = Wd[buf][kk][tx + 16 * c];
#pragma unroll
            for (int rp = 0; rp < 4; rp++)
#pragma unroll
                for (int c = 0; c < 8; c++)
                    acc[rp][c] = fmaf32x2(wd[c], xr[rp], acc[rp][c]);
        }

        if (more) { buf ^= 1; SSTORE(buf); __syncthreads(); }
    }
#undef GLOAD
#undef SSTORE

    // epilogue: K-major partial store. col = bm + tx + 16c -> kgrp = bm/16+c
    float* dstz = g_P + blockIdx.z * PART;
#pragma unroll
    for (int c = 0; c < 8; c++) {
        float* d = dstz + (bm / 16 + c) * (NROWS * DD) + tx;
#pragma unroll
        for (int rp = 0; rp < 4; rp++) {
            const int r0 = bn + 8 * ty + 2 * rp;
            d[r0 * DD]       = lo32(acc[rp][c]);
            d[(r0 + 1) * DD] = hi32(acc[rp][c]);
        }
    }
}

// ---------------------------------------------------------------------------
// Kernel 2: g_feat = sum of 4 partials + bias (k-major). 512 blocks x 256.
// ---------------------------------------------------------------------------
__global__ __launch_bounds__(256)
void sumfeat_kernel(const float* __restrict__ b) {
    const int idx = blockIdx.x * 256 + threadIdx.x;     // float4 index
    const int kg = idx >> 11;                           // 2048 float4 per k
    const int q = idx & 3;
    float4 v0 = ((const float4*)g_P)[idx];
    float4 v1 = ((const float4*)(g_P + PART))[idx];
    float4 v2 = ((const float4*)(g_P + 2 * PART))[idx];
    float4 v3 = ((const float4*)(g_P + 3 * PART))[idx];
    float4 bb = *(const float4*)&b[kg * DD + q * 4];
    float4 o;
    o.x = v0.x + v1.x + v2.x + v3.x + bb.x;
    o.y = v0.y + v1.y + v2.y + v3.y + bb.y;
    o.z = v0.z + v1.z + v2.z + v3.z + bb.z;
    o.w = v0.w + v1.w + v2.w + v3.w + bb.w;
    ((float4*)g_feat)[idx] = o;
}

// ---------------------------------------------------------------------------
// Kernel 3: symmetric pairwise, k-grouped. grid (36 units, 16 kgroups),
// 256 thr. Each block: 4 consecutive k's of one (a,bt) unit with cp.async
// double-buffered stripes (positive slabs; fi sign-flipped in registers).
// ---------------------------------------------------------------------------
__global__ __launch_bounds__(256)
void pairwise_kernel() {
    __shared__ __align__(16) ull sF[2][2][T * 8];   // [bank][A/B] 16 KB
    __shared__ float sE[2 * T * 32];                // 16 KB
    __shared__ float sTot[8][32];

    const int u  = blockIdx.x;
    const int kg = blockIdx.y;
    const int a  = c_ua[u];
    const int bt = c_ub[u];
    const bool diag = (a == bt);

    const int tid = threadIdx.x;
    const int lane = tid & 31, w = tid >> 5;
    const int h = w >> 2, s = w & 3;
    const int iL = h * 32 + lane;
    const int jb = s * 16;

#define ISSUE(t) do {                                                        \
    const int _k = kg * 4 + (t);                                             \
    const int _bk = (t) & 1;                                                 \
    CPA16(su32((char*)&sF[_bk][0][0] + tid * 16),                            \
          g_feat + _k * 8192 + a * 1024 + tid * 4);                          \
    if (!diag)                                                               \
        CPA16(su32((char*)&sF[_bk][1][0] + tid * 16),                        \
              g_feat + _k * 8192 + bt * 1024 + tid * 4);                     \
} while (0)

    ISSUE(0); CPA_COMMIT();

    const ull SGN = 0x8000000080000000ULL;
    const ull ABSM = 0x7fffffff7fffffffULL;

    for (int t = 0; t < 4; t++) {
        CPA_WAIT0();
        __syncthreads();
        if (t < 3) { ISSUE(t + 1); CPA_COMMIT(); }

        const int bank = t & 1;
        const ull* slabA = sF[bank][0];
        const ull* slabB = diag ? sF[bank][0] : sF[bank][1];

        ull fi[8];
        {
            const ulonglong2* p = (const ulonglong2*)&slabA[iL * 8];
            ulonglong2 f0 = p[0], f1 = p[1], f2 = p[2], f3 = p[3];
            fi[0] = f0.x ^ SGN; fi[1] = f0.y ^ SGN;
            fi[2] = f1.x ^ SGN; fi[3] = f1.y ^ SGN;
            fi[4] = f2.x ^ SGN; fi[5] = f2.y ^ SGN;
            fi[6] = f3.x ^ SGN; fi[7] = f3.y ^ SGN;
        }

        float ti = 0.f;
#pragma unroll 4
        for (int jj = 0; jj < 16; jj++) {
            const int j = jb + jj;
            const ulonglong2* row = (const ulonglong2*)&slabB[j * 8];
            ulonglong2 q0 = row[0], q1 = row[1], q2 = row[2], q3 = row[3];
            ull d0 = addf32x2(fi[0], q0.x) & ABSM;
            ull d1 = addf32x2(fi[1], q0.y) & ABSM;
            ull d2 = addf32x2(fi[2], q1.x) & ABSM;
            ull d3 = addf32x2(fi[3], q1.y) & ABSM;
            ull d4 = addf32x2(fi[4], q2.x) & ABSM;
            ull d5 = addf32x2(fi[5], q2.y) & ABSM;
            ull d6 = addf32x2(fi[6], q3.x) & ABSM;
            ull d7 = addf32x2(fi[7], q3.y) & ABSM;
            ull sm = addf32x2(addf32x2(addf32x2(d0, d1), addf32x2(d2, d3)),
                              addf32x2(addf32x2(d4, d5), addf32x2(d6, d7)));
            float e = ex2f((lo32(sm) + hi32(sm)) * NLOG2E);
            ti += e;
            if (!diag) sE[h * (T * 32) + j * 32 + lane] = e;
        }
        sTot[w][lane] = ti;
        __syncthreads();

        const int k = kg * 4 + t;
        if (!diag) {
            // tj: warp w reduces columns j = 8w..8w+7 over 64 i
#pragma unroll
            for (int jj = 0; jj < 8; jj++) {
                const int j = w * 8 + jj;
                float v = sE[j * 32 + lane] + sE[T * 32 + j * 32 + lane];
                v += __shfl_xor_sync(0xffffffffu, v, 16);
                v += __shfl_xor_sync(0xffffffffu, v, 8);
                v += __shfl_xor_sync(0xffffffffu, v, 4);
                v += __shfl_xor_sync(0xffffffffu, v, 2);
                v += __shfl_xor_sync(0xffffffffu, v, 1);
                if (lane == 0)
                    g_part[a * PARTO + k * NROWS + bt * T + j] = v;
            }
        }
        if (tid < 64) {
            const int hh = tid >> 5, l = tid & 31;
            float tt = sTot[hh * 4 + 0][l] + sTot[hh * 4 + 1][l] +
                       sTot[hh * 4 + 2][l] + sTot[hh * 4 + 3][l];
            g_part[bt * PARTO + k * NROWS + a * T + tid] = tt;
        }
        // next iteration's top barrier protects sE/sTot reuse
    }
#undef ISSUE
}

// ---------------------------------------------------------------------------
// Kernel 4: finalize o_b + x copy. grid 256 x 256 (65536 threads).
// ---------------------------------------------------------------------------
__global__ __launch_bounds__(256)
void final_kernel(const float* __restrict__ x, float* __restrict__ out) {
    const int g = blockIdx.x * 256 + threadIdx.x;    // 0..65535

    ((float4*)out)[(g >> 7) * 144 + (g & 127)] = ((const float4*)x)[g];

    if (g < NROWS * KK) {
        const int k = g >> 9;
        const int i = g & 511;
        float t = -1.0f;
#pragma unroll
        for (int p = 0; p < 8; p++) t += g_part[p * PARTO + k * NROWS + i];
        out[i * OUTW + INSIZE + k] = t;
    }
}

// ---------------------------------------------------------------------------
extern "C" void kernel_launch(void* const* d_in, const int* in_sizes, int n_in,
                              void* d_out, int out_size) {
    const float* x = (const float*)d_in[0];   // [512,512]
    const float* W = (const float*)d_in[1];   // [1024,512]
    const float* b = (const float*)d_in[2];   // [1024]
    float* out = (float*)d_out;               // [512,576]

    gemm_kernel<<<dim3(8, 8, 4), 128>>>(x, W);
    sumfeat_kernel<<<512, 256>>>(b);
    pairwise_kernel<<<dim3(36, 16), 256>>>();
    final_kernel<<<256, 256>>>(x, out);
}

// round 11
// speedup vs baseline: 1.5467x; 1.0006x over previous
#include <cuda_runtime.h>
#include <cstdint>

#define NROWS  512
#define INSIZE 512
#define KK     64
#define DD     16
#define MM     (KK * DD)        // 1024
#define OUTW   (INSIZE + KK)    // 576
#define BK     16
#define T      64
#define PART   (NROWS * MM)     // one split-K partial, K-major [k][row][d]
#define PARTO  (NROWS * KK)     // one output-slot partial [k][i]

typedef unsigned long long ull;

__device__ float g_P[4 * PART];          // split-K partials, K-major  8 MB
__device__ float g_feat[NROWS * MM];     // k-major feat (+bias)       2 MB
__device__ float g_part[8 * PARTO];      // output slots               1 MB

// 36 tile-units: 8 diagonal + 28 upper-triangle
__constant__ int c_ua[36] = {0,1,2,3,4,5,6,7, 0,0,0,0,0,0,0, 1,1,1,1,1,1,
                             2,2,2,2,2, 3,3,3,3, 4,4,4, 5,5, 6};
__constant__ int c_ub[36] = {0,1,2,3,4,5,6,7, 1,2,3,4,5,6,7, 2,3,4,5,6,7,
                             3,4,5,6,7, 4,5,6,7, 5,6,7, 6,7, 7};

// ---------------------------------------------------------------------------
// helpers
// ---------------------------------------------------------------------------
__device__ __forceinline__ ull addf32x2(ull a, ull b) {
    ull r;
    asm("add.rn.f32x2 %0, %1, %2;" : "=l"(r) : "l"(a), "l"(b));
    return r;
}
__device__ __forceinline__ ull fmaf32x2(ull a, ull b, ull c) {
    ull r;
    asm("fma.rn.f32x2 %0, %1, %2, %3;" : "=l"(r) : "l"(a), "l"(b), "l"(c));
    return r;
}
__device__ __forceinline__ float lo32(ull v) {
    return __uint_as_float((unsigned int)v);
}
__device__ __forceinline__ float hi32(ull v) {
    return __uint_as_float((unsigned int)(v >> 32));
}
__device__ __forceinline__ float ex2f(float v) {
    float r;
    asm("ex2.approx.f32 %0, %1;" : "=f"(r) : "f"(v));
    return r;
}
__device__ __forceinline__ unsigned su32(const void* p) {
    return (unsigned)__cvta_generic_to_shared(p);
}
#define CPA16(dst, src) \
    asm volatile("cp.async.cg.shared.global [%0], [%1], 16;" :: "r"(dst), "l"(src))
#define CPA_COMMIT() asm volatile("cp.async.commit_group;")
#define CPA_WAIT0()  asm volatile("cp.async.wait_group 0;")

#define NLOG2E (-1.4426950408889634f)

// ---------------------------------------------------------------------------
// Kernel 1: split-K(4) GEMM partials, 8x8 micro-tile. (unchanged from R10)
// ---------------------------------------------------------------------------
__global__ __launch_bounds__(128)
void gemm_kernel(const float* __restrict__ x, const float* __restrict__ W) {
    __shared__ __align__(16) float Xs[2][BK][68];   // transposed x, padded
    __shared__ __align__(16) ull   Wd[2][BK][129];  // dup W cols, padded

    const int bm = blockIdx.x * 128;
    const int bn = blockIdx.y * 64;
    const int kz = blockIdx.z * 128;
    const int tid = threadIdx.x;
    const int tx = tid & 15, ty = tid >> 4;

    ull acc[4][8];
#pragma unroll
    for (int rp = 0; rp < 4; rp++)
#pragma unroll
        for (int c = 0; c < 8; c++) acc[rp][c] = 0ULL;

    float4 xs4[2], ws4[4];

#define GLOAD(step) do {                                                     \
    _Pragma("unroll")                                                        \
    for (int j = 0; j < 2; j++) {                                            \
        int idx = tid + j * 128; int row = idx >> 2, kq = idx & 3;           \
        xs4[j] = *(const float4*)&x[(bn + row) * INSIZE + kz +               \
                                    (step) * BK + kq * 4];                   \
    }                                                                        \
    _Pragma("unroll")                                                        \
    for (int j = 0; j < 4; j++) {                                            \
        int idx = tid + j * 128; int col = idx >> 2, kq = idx & 3;           \
        ws4[j] = *(const float4*)&W[(bm + col) * INSIZE + kz +               \
                                    (step) * BK + kq * 4];                   \
    }                                                                        \
} while (0)

#define SSTORE(bf) do {                                                      \
    _Pragma("unroll")                                                        \
    for (int j = 0; j < 2; j++) {                                            \
        int idx = tid + j * 128; int row = idx >> 2, kq = idx & 3;           \
        float v[4] = {xs4[j].x, xs4[j].y, xs4[j].z, xs4[j].w};               \
        _Pragma("unroll")                                                    \
        for (int jj = 0; jj < 4; jj++) Xs[bf][kq * 4 + jj][row] = v[jj];     \
    }                                                                        \
    _Pragma("unroll")                                                        \
    for (int j = 0; j < 4; j++) {                                            \
        int idx = tid + j * 128; int col = idx >> 2, kq = idx & 3;           \
        float v[4] = {ws4[j].x, ws4[j].y, ws4[j].z, ws4[j].w};               \
        _Pragma("unroll")                                                    \
        for (int jj = 0; jj < 4; jj++)                                       \
            *(float2*)&Wd[bf][kq * 4 + jj][col] = make_float2(v[jj], v[jj]); \
    }                                                                        \
} while (0)

    GLOAD(0); SSTORE(0); __syncthreads();
    int buf = 0;

    for (int step = 1; step <= 8; step++) {
        const bool more = (step < 8);
        if (more) GLOAD(step);

#pragma unroll
        for (int kk = 0; kk < BK; kk++) {
            ulonglong2 xp0 = *(const ulonglong2*)&Xs[buf][kk][8 * ty];
            ulonglong2 xp1 = *(const ulonglong2*)&Xs[buf][kk][8 * ty + 4];
            ull xr[4] = {xp0.x, xp0.y, xp1.x, xp1.y};
            ull wd[8];
#pragma unroll
            for (int c = 0; c < 8; c++) wd[c] = Wd[buf][kk][tx + 16 * c];
#pragma unroll
            for (int rp = 0; rp < 4; rp++)
#pragma unroll
                for (int c = 0; c < 8; c++)
                    acc[rp][c] = fmaf32x2(wd[c], xr[rp], acc[rp][c]);
        }

        if (more) { buf ^= 1; SSTORE(buf); __syncthreads(); }
    }
#undef GLOAD
#undef SSTORE

    float* dstz = g_P + blockIdx.z * PART;
#pragma unroll
    for (int c = 0; c < 8; c++) {
        float* d = dstz + (bm / 16 + c) * (NROWS * DD) + tx;
#pragma unroll
        for (int rp = 0; rp < 4; rp++) {
            const int r0 = bn + 8 * ty + 2 * rp;
            d[r0 * DD]       = lo32(acc[rp][c]);
            d[(r0 + 1) * DD] = hi32(acc[rp][c]);
        }
    }
}

// ---------------------------------------------------------------------------
// Kernel 2: g_feat = sum of 4 partials + bias (k-major). (unchanged)
// ---------------------------------------------------------------------------
__global__ __launch_bounds__(256)
void sumfeat_kernel(const float* __restrict__ b) {
    const int idx = blockIdx.x * 256 + threadIdx.x;
    const int kg = idx >> 11;
    const int q = idx & 3;
    float4 v0 = ((const float4*)g_P)[idx];
    float4 v1 = ((const float4*)(g_P + PART))[idx];
    float4 v2 = ((const float4*)(g_P + 2 * PART))[idx];
    float4 v3 = ((const float4*)(g_P + 3 * PART))[idx];
    float4 bb = *(const float4*)&b[kg * DD + q * 4];
    float4 o;
    o.x = v0.x + v1.x + v2.x + v3.x + bb.x;
    o.y = v0.y + v1.y + v2.y + v3.y + bb.y;
    o.z = v0.z + v1.z + v2.z + v3.z + bb.z;
    o.w = v0.w + v1.w + v2.w + v3.w + bb.w;
    ((float4*)g_feat)[idx] = o;
}

// ---------------------------------------------------------------------------
// Kernel 3: symmetric pairwise, k-grouped, cp.async stripes. (unchanged)
// ---------------------------------------------------------------------------
__global__ __launch_bounds__(256)
void pairwise_kernel() {
    __shared__ __align__(16) ull sF[2][2][T * 8];
    __shared__ float sE[2 * T * 32];
    __shared__ float sTot[8][32];

    const int u  = blockIdx.x;
    const int kg = blockIdx.y;
    const int a  = c_ua[u];
    const int bt = c_ub[u];
    const bool diag = (a == bt);

    const int tid = threadIdx.x;
    const int lane = tid & 31, w = tid >> 5;
    const int h = w >> 2, s = w & 3;
    const int iL = h * 32 + lane;
    const int jb = s * 16;

#define ISSUE(t) do {                                                        \
    const int _k = kg * 4 + (t);                                             \
    const int _bk = (t) & 1;                                                 \
    CPA16(su32((char*)&sF[_bk][0][0] + tid * 16),                            \
          g_feat + _k * 8192 + a * 1024 + tid * 4);                          \
    if (!diag)                                                               \
        CPA16(su32((char*)&sF[_bk][1][0] + tid * 16),                        \
              g_feat + _k * 8192 + bt * 1024 + tid * 4);                     \
} while (0)

    ISSUE(0); CPA_COMMIT();

    const ull SGN = 0x8000000080000000ULL;
    const ull ABSM = 0x7fffffff7fffffffULL;

    for (int t = 0; t < 4; t++) {
        CPA_WAIT0();
        __syncthreads();
        if (t < 3) { ISSUE(t + 1); CPA_COMMIT(); }

        const int bank = t & 1;
        const ull* slabA = sF[bank][0];
        const ull* slabB = diag ? sF[bank][0] : sF[bank][1];

        ull fi[8];
        {
            const ulonglong2* p = (const ulonglong2*)&slabA[iL * 8];
            ulonglong2 f0 = p[0], f1 = p[1], f2 = p[2], f3 = p[3];
            fi[0] = f0.x ^ SGN; fi[1] = f0.y ^ SGN;
            fi[2] = f1.x ^ SGN; fi[3] = f1.y ^ SGN;
            fi[4] = f2.x ^ SGN; fi[5] = f2.y ^ SGN;
            fi[6] = f3.x ^ SGN; fi[7] = f3.y ^ SGN;
        }

        float ti = 0.f;
#pragma unroll 4
        for (int jj = 0; jj < 16; jj++) {
            const int j = jb + jj;
            const ulonglong2* row = (const ulonglong2*)&slabB[j * 8];
            ulonglong2 q0 = row[0], q1 = row[1], q2 = row[2], q3 = row[3];
            ull d0 = addf32x2(fi[0], q0.x) & ABSM;
            ull d1 = addf32x2(fi[1], q0.y) & ABSM;
            ull d2 = addf32x2(fi[2], q1.x) & ABSM;
            ull d3 = addf32x2(fi[3], q1.y) & ABSM;
            ull d4 = addf32x2(fi[4], q2.x) & ABSM;
            ull d5 = addf32x2(fi[5], q2.y) & ABSM;
            ull d6 = addf32x2(fi[6], q3.x) & ABSM;
            ull d7 = addf32x2(fi[7], q3.y) & ABSM;
            ull sm = addf32x2(addf32x2(addf32x2(d0, d1), addf32x2(d2, d3)),
                              addf32x2(addf32x2(d4, d5), addf32x2(d6, d7)));
            float e = ex2f((lo32(sm) + hi32(sm)) * NLOG2E);
            ti += e;
            if (!diag) sE[h * (T * 32) + j * 32 + lane] = e;
        }
        sTot[w][lane] = ti;
        __syncthreads();

        const int k = kg * 4 + t;
        if (!diag) {
#pragma unroll
            for (int jj = 0; jj < 8; jj++) {
                const int j = w * 8 + jj;
                float v = sE[j * 32 + lane] + sE[T * 32 + j * 32 + lane];
                v += __shfl_xor_sync(0xffffffffu, v, 16);
                v += __shfl_xor_sync(0xffffffffu, v, 8);
                v += __shfl_xor_sync(0xffffffffu, v, 4);
                v += __shfl_xor_sync(0xffffffffu, v, 2);
                v += __shfl_xor_sync(0xffffffffu, v, 1);
                if (lane == 0)
                    g_part[a * PARTO + k * NROWS + bt * T + j] = v;
            }
        }
        if (tid < 64) {
            const int hh = tid >> 5, l = tid & 31;
            float tt = sTot[hh * 4 + 0][l] + sTot[hh * 4 + 1][l] +
                       sTot[hh * 4 + 2][l] + sTot[hh * 4 + 3][l];
            g_part[bt * PARTO + k * NROWS + a * T + tid] = tt;
        }
    }
#undef ISSUE
}

// ---------------------------------------------------------------------------
// Kernel 4: finalize. 64 blocks x 256. Blocks 0-31: transpose-reduce 16 rows
// of o_b each via smem (coalesced g_part reads, sector-perfect out writes).
// All blocks: x -> out copy (4 float4 / thread).
// ---------------------------------------------------------------------------
__global__ __launch_bounds__(256)
void final_kernel(const float* __restrict__ x, float* __restrict__ out) {
    __shared__ float s[64][17];     // [k][ii], padded
    const int blk = blockIdx.x;
    const int tid = threadIdx.x;

    // x copy: 65536 float4 over 64 blocks = 1024/block = 4/thread
    {
        const float4* xin = (const float4*)x;
        float4* o4 = (float4*)out;
#pragma unroll
        for (int v = 0; v < 4; v++) {
            int idx = blk * 1024 + v * 256 + tid;
            o4[(idx >> 7) * 144 + (idx & 127)] = xin[idx];
        }
    }

    if (blk < 32) {
        const int i0 = blk * 16;
        // phase 1: s[k][ii] = sum_p g_part[p][k*512 + i0+ii] - 1
        const int ii = tid & 15, kq = tid >> 4;     // kq 0..15
#pragma unroll
        for (int it = 0; it < 4; it++) {
            const int k = it * 16 + kq;
            float t = -1.0f;
#pragma unroll
            for (int p = 0; p < 8; p++)
                t += g_part[p * PARTO + k * NROWS + i0 + ii];
            s[k][ii] = t;
        }
        __syncthreads();

        // phase 2: thread (ii2,q) writes out[(i0+ii2)*576+512+q*4 .. +3]
        const int ii2 = tid >> 4, q = tid & 15;
        float4 o;
        o.x = s[q * 4 + 0][ii2];
        o.y = s[q * 4 + 1][ii2];
        o.z = s[q * 4 + 2][ii2];
        o.w = s[q * 4 + 3][ii2];
        *(float4*)&out[(i0 + ii2) * OUTW + INSIZE + q * 4] = o;
    }
}

// ---------------------------------------------------------------------------
extern "C" void kernel_launch(void* const* d_in, const int* in_sizes, int n_in,
                              void* d_out, int out_size) {
    const float* x = (const float*)d_in[0];   // [512,512]
    const float* W = (const float*)d_in[1];   // [1024,512]
    const float* b = (const float*)d_in[2];   // [1024]
    float* out = (float*)d_out;               // [512,576]

    gemm_kernel<<<dim3(8, 8, 4), 128>>>(x, W);
    sumfeat_kernel<<<512, 256>>>(b);
    pairwise_kernel<<<dim3(36, 16), 256>>>();
    final_kernel<<<64, 256>>>(x, out);
}